// round 3
// baseline (speedup 1.0000x reference)
#include <cuda_runtime.h>

// EMA over frames: out[b,0] = x[b,0]; out[b,t] = 0.99*out[b,t-1] + 0.01*x[b,t]
// Shapes fixed: B=4, T=128, N=256, D=768, fp32.
// Pure HBM stream: 402 MB read + 402 MB write; bound by mixed-R/W DRAM BW.

#define EMA_B 4
#define EMA_T 128
#define EMA_N 256
#define EMA_D 768

__global__ void __launch_bounds__(256, 8)
ema_scan_kernel(const float4* __restrict__ x, float4* __restrict__ out)
{
    constexpr int ND4  = (EMA_N * EMA_D) / 4;   // 49152 float4 per (b,t) slab
    constexpr int TND4 = EMA_T * ND4;

    const int tid = blockIdx.x * blockDim.x + threadIdx.x;   // 0 .. B*ND4-1
    const int b   = tid / ND4;
    const int r   = tid - b * ND4;
    if (b >= EMA_B) return;

    const float4* xp = x   + (long long)b * TND4 + r;
    float4*       op = out + (long long)b * TND4 + r;

    const float decay = 0.99f;
    const float omd   = 0.01f;

    // t = 0: copy. Load evict-first (read-once data); store default write-back.
    float4 mem = __ldcs(xp);
    op[0] = mem;

    // t = 1..127: interleaved fma scan (R1 structure — best measured).
    // unroll 4 gives MLP ~4, already more than enough to cover DRAM latency.
#pragma unroll 4
    for (int t = 1; t < EMA_T; ++t) {
        float4 v = __ldcs(xp + (long long)t * ND4);
        mem.x = fmaf(decay, mem.x, omd * v.x);
        mem.y = fmaf(decay, mem.y, omd * v.y);
        mem.z = fmaf(decay, mem.z, omd * v.z);
        mem.w = fmaf(decay, mem.w, omd * v.w);
        op[(long long)t * ND4] = mem;
    }
}

extern "C" void kernel_launch(void* const* d_in, const int* in_sizes, int n_in,
                              void* d_out, int out_size)
{
    const float4* x   = (const float4*)d_in[0];
    float4*       out = (float4*)d_out;

    constexpr int total_f4 = (EMA_B * EMA_N * EMA_D) / 4;  // 196608
    constexpr int threads  = 256;
    constexpr int blocks   = total_f4 / threads;           // 768

    ema_scan_kernel<<<blocks, threads>>>(x, out);
}

// round 4
// speedup vs baseline: 1.0515x; 1.0515x over previous
#include <cuda_runtime.h>

// EMA over frames: out[b,0] = x[b,0]; out[b,t] = 0.99*out[b,t-1] + 0.01*x[b,t]
// Shapes fixed: B=4, T=128, N=256, D=768, fp32.
// Pure HBM stream: 402 MB read + 402 MB write; bound by mixed-R/W DRAM BW.
// R1 structure (plain LDG/STG — all .cs variants measured slower), unroll 8.

#define EMA_B 4
#define EMA_T 128
#define EMA_N 256
#define EMA_D 768

__global__ void __launch_bounds__(256, 8)
ema_scan_kernel(const float4* __restrict__ x, float4* __restrict__ out)
{
    constexpr int ND4  = (EMA_N * EMA_D) / 4;   // 49152 float4 per (b,t) slab
    constexpr int TND4 = EMA_T * ND4;

    const int tid = blockIdx.x * blockDim.x + threadIdx.x;   // 0 .. B*ND4-1
    const int b   = tid / ND4;
    const int r   = tid - b * ND4;
    if (b >= EMA_B) return;

    const float4* xp = x   + (long long)b * TND4 + r;
    float4*       op = out + (long long)b * TND4 + r;

    const float decay = 0.99f;
    const float omd   = 0.01f;

    // t = 0: copy
    float4 mem = xp[0];
    op[0] = mem;

    // t = 1..127: fma scan. Loads independent across t; unroll 8 lets ptxas
    // front-batch up to 8 LDG.128s per iteration for larger read bursts.
#pragma unroll 8
    for (int t = 1; t < EMA_T; ++t) {
        float4 v = xp[(long long)t * ND4];
        mem.x = fmaf(decay, mem.x, omd * v.x);
        mem.y = fmaf(decay, mem.y, omd * v.y);
        mem.z = fmaf(decay, mem.z, omd * v.z);
        mem.w = fmaf(decay, mem.w, omd * v.w);
        op[(long long)t * ND4] = mem;
    }
}

extern "C" void kernel_launch(void* const* d_in, const int* in_sizes, int n_in,
                              void* d_out, int out_size)
{
    const float4* x   = (const float4*)d_in[0];
    float4*       out = (float4*)d_out;

    constexpr int total_f4 = (EMA_B * EMA_N * EMA_D) / 4;  // 196608
    constexpr int threads  = 256;
    constexpr int blocks   = total_f4 / threads;           // 768

    ema_scan_kernel<<<blocks, threads>>>(x, out);
}

// round 5
// speedup vs baseline: 1.0547x; 1.0031x over previous
#include <cuda_runtime.h>

// EMA over frames: out[b,0] = x[b,0]; out[b,t] = 0.99*out[b,t-1] + 0.01*x[b,t]
// Shapes fixed: B=4, T=128, N=256, D=768, fp32.
//
// Pure HBM stream: 402 MB read + 402 MB write, zero reuse -> bound by mixed
// R/W DRAM bandwidth. Achieves ~6.7 TB/s demanded bytes (~84% of spec), which
// is the practical ceiling for a 50/50 stream on this part.
//
// Measured config sweep: plain LDG/STG + unroll 4 is best.
//   .cs hints (any combination): -3..-13% DRAM throughput (LTS evict-first
//   perturbs DRAM read scheduling on sm_103a). unroll 8: neutral.

#define EMA_B 4
#define EMA_T 128
#define EMA_N 256
#define EMA_D 768

__global__ void __launch_bounds__(256, 8)
ema_scan_kernel(const float4* __restrict__ x, float4* __restrict__ out)
{
    constexpr int ND4  = (EMA_N * EMA_D) / 4;   // 49152 float4 per (b,t) slab
    constexpr int TND4 = EMA_T * ND4;

    const int tid = blockIdx.x * blockDim.x + threadIdx.x;   // 0 .. B*ND4-1
    const int b   = tid / ND4;
    const int r   = tid - b * ND4;
    if (b >= EMA_B) return;

    const float4* xp = x   + (long long)b * TND4 + r;
    float4*       op = out + (long long)b * TND4 + r;

    const float decay = 0.99f;
    const float omd   = 0.01f;

    // t = 0: copy
    float4 mem = xp[0];
    op[0] = mem;

    // t = 1..127: fma scan. Loads independent across t; unroll 4 front-batches
    // 4 LDG.128s per thread (MLP ~4) — ample to cover DRAM latency at this
    // occupancy (41.5 warps/SM).
#pragma unroll 4
    for (int t = 1; t < EMA_T; ++t) {
        float4 v = xp[(long long)t * ND4];
        mem.x = fmaf(decay, mem.x, omd * v.x);
        mem.y = fmaf(decay, mem.y, omd * v.y);
        mem.z = fmaf(decay, mem.z, omd * v.z);
        mem.w = fmaf(decay, mem.w, omd * v.w);
        op[(long long)t * ND4] = mem;
    }
}

extern "C" void kernel_launch(void* const* d_in, const int* in_sizes, int n_in,
                              void* d_out, int out_size)
{
    const float4* x   = (const float4*)d_in[0];
    float4*       out = (float4*)d_out;

    constexpr int total_f4 = (EMA_B * EMA_N * EMA_D) / 4;  // 196608
    constexpr int threads  = 256;
    constexpr int blocks   = total_f4 / threads;           // 768

    ema_scan_kernel<<<blocks, threads>>>(x, out);
}

// round 6
// speedup vs baseline: 1.0704x; 1.0148x over previous
#include <cuda_runtime.h>

// EMA over frames: out[b,0] = x[b,0]; out[b,t] = 0.99*out[b,t-1] + 0.01*x[b,t]
// Shapes fixed: B=4, T=128, N=256, D=768, fp32.
//
// Pure HBM stream: 402 MB read + 402 MB write, zero reuse. Bound by mixed
// R/W DRAM bandwidth; achieves 6.1-6.7 TB/s demanded bytes (76-84% of spec),
// which is the practical ceiling for a 50/50 stream. Bench-to-bench variance
// is ~±5% (NAT DVFS); configs within that band are equivalent.
//
// Sweep results: plain LDG/STG + unroll 4 best; .cs on loads genuinely worse
// (ptxas drops MLP, -8%); .cs both / unroll 8: noise-equivalent.

#define EMA_B 4
#define EMA_T 128
#define EMA_N 256
#define EMA_D 768

__global__ void __launch_bounds__(256, 8)
ema_scan_kernel(const float4* __restrict__ x, float4* __restrict__ out)
{
    constexpr int ND4  = (EMA_N * EMA_D) / 4;   // 49152 float4 per (b,t) slab
    constexpr int TND4 = EMA_T * ND4;

    const int tid = blockIdx.x * blockDim.x + threadIdx.x;   // 0 .. B*ND4-1
    const int b   = tid / ND4;
    const int r   = tid - b * ND4;
    if (b >= EMA_B) return;

    const float4* xp = x   + (long long)b * TND4 + r;
    float4*       op = out + (long long)b * TND4 + r;

    const float decay = 0.99f;
    const float omd   = 0.01f;

    // t = 0: copy
    float4 mem = xp[0];
    op[0] = mem;

    // t = 1..127: fma scan. Loads independent across t; unroll 4 front-batches
    // 4 LDG.128s per thread (MLP ~4), ample to cover DRAM latency at 41.5
    // resident warps/SM. Warp accesses at fixed t are fully coalesced.
#pragma unroll 4
    for (int t = 1; t < EMA_T; ++t) {
        float4 v = xp[(long long)t * ND4];
        mem.x = fmaf(decay, mem.x, omd * v.x);
        mem.y = fmaf(decay, mem.y, omd * v.y);
        mem.z = fmaf(decay, mem.z, omd * v.z);
        mem.w = fmaf(decay, mem.w, omd * v.w);
        op[(long long)t * ND4] = mem;
    }
}

extern "C" void kernel_launch(void* const* d_in, const int* in_sizes, int n_in,
                              void* d_out, int out_size)
{
    const float4* x   = (const float4*)d_in[0];
    float4*       out = (float4*)d_out;

    constexpr int total_f4 = (EMA_B * EMA_N * EMA_D) / 4;  // 196608
    constexpr int threads  = 256;
    constexpr int blocks   = total_f4 / threads;           // 768

    ema_scan_kernel<<<blocks, threads>>>(x, out);
}